// round 1
// baseline (speedup 1.0000x reference)
#include <cuda_runtime.h>
#include <cuda_bf16.h>
#include <math.h>

// Problem constants (from reference): N=50000 nodes, E=800000 edges, D_IN=512, D_HID=256
#define MAX_N 50000
#define MAX_E 800000
#define DHID 256

// Scratch (device globals; allocation inside kernel_launch is forbidden)
__device__ float g_dinv[MAX_N];            // degree -> rsqrt(degree), in place
__device__ float g_coef[MAX_E];            // dinv[src]*dinv[dst], reused both layers
__device__ float g_h1[(size_t)MAX_N * DHID];    // x @ W1
__device__ float g_agg1[(size_t)MAX_N * DHID];  // aggregated layer 1 (pre-relu, bias included)
__device__ float g_h2[(size_t)MAX_N * DHID];    // relu(agg1) @ W2
__device__ float g_agg2[(size_t)MAX_N * DHID];  // aggregated layer 2 output

// ---------------------------------------------------------------------------
// degree / normalization
// ---------------------------------------------------------------------------
__global__ void init_deg_kernel(float* deg, int n) {
    int i = blockIdx.x * blockDim.x + threadIdx.x;
    if (i < n) deg[i] = 1.0f;  // self-loop
}

__global__ void add_deg_kernel(float* deg, const int* __restrict__ dst, int e) {
    int i = blockIdx.x * blockDim.x + threadIdx.x;
    if (i < e) atomicAdd(&deg[dst[i]], 1.0f);
}

__global__ void dinv_kernel(float* deg, int n) {
    int i = blockIdx.x * blockDim.x + threadIdx.x;
    if (i < n) deg[i] = rsqrtf(deg[i]);  // deg >= 1 always (self-loop)
}

__global__ void coef_kernel(const float* __restrict__ dinv,
                            const int* __restrict__ src,
                            const int* __restrict__ dst,
                            float* __restrict__ coef, int e) {
    int i = blockIdx.x * blockDim.x + threadIdx.x;
    if (i < e) coef[i] = dinv[src[i]] * dinv[dst[i]];
}

// ---------------------------------------------------------------------------
// GEMM: C[M,N] = op(A)[M,K] @ B[K,N], fp32, 64x64 block tile, 4x4 per thread.
// RELU applies relu to A elements on load (fuses layer-1 activation into GEMM2).
// N and K are multiples of 4 (N=256, K=512/256); only M has edge handling.
// ---------------------------------------------------------------------------
template <bool RELU>
__global__ __launch_bounds__(256)
void gemm64x64_kernel(const float* __restrict__ A, const float* __restrict__ B,
                      float* __restrict__ C, int M, int K, int N) {
    __shared__ float As[16][68];  // [k][m], padded
    __shared__ float Bs[16][68];  // [k][n], padded

    const int tid = threadIdx.x;
    const int tx = tid & 15;       // 0..15 -> N direction
    const int ty = tid >> 4;       // 0..15 -> M direction
    const int rowBase = blockIdx.y * 64;
    const int colBase = blockIdx.x * 64;

    // A-tile load map: thread -> (row = tid/4 in [0,64), col4 = (tid%4)*4)
    const int ar = tid >> 2;
    const int ac = (tid & 3) << 2;
    // B-tile load map: thread -> (row = tid/16 in [0,16), col4 = (tid%16)*4)
    const int br = tid >> 4;
    const int bc = (tid & 15) << 2;

    float acc[4][4];
#pragma unroll
    for (int i = 0; i < 4; i++)
#pragma unroll
        for (int j = 0; j < 4; j++) acc[i][j] = 0.0f;

    for (int k0 = 0; k0 < K; k0 += 16) {
        // Load A tile (transposed into As[k][m])
        float4 av;
        const int arow = rowBase + ar;
        if (arow < M) {
            av = *reinterpret_cast<const float4*>(A + (size_t)arow * K + k0 + ac);
        } else {
            av = make_float4(0.f, 0.f, 0.f, 0.f);
        }
        if (RELU) {
            av.x = fmaxf(av.x, 0.f); av.y = fmaxf(av.y, 0.f);
            av.z = fmaxf(av.z, 0.f); av.w = fmaxf(av.w, 0.f);
        }
        As[ac + 0][ar] = av.x;
        As[ac + 1][ar] = av.y;
        As[ac + 2][ar] = av.z;
        As[ac + 3][ar] = av.w;

        // Load B tile
        float4 bv = *reinterpret_cast<const float4*>(B + (size_t)(k0 + br) * N + colBase + bc);
        Bs[br][bc + 0] = bv.x;
        Bs[br][bc + 1] = bv.y;
        Bs[br][bc + 2] = bv.z;
        Bs[br][bc + 3] = bv.w;

        __syncthreads();

#pragma unroll
        for (int k = 0; k < 16; k++) {
            float a[4], b[4];
#pragma unroll
            for (int i = 0; i < 4; i++) a[i] = As[k][ty * 4 + i];
#pragma unroll
            for (int j = 0; j < 4; j++) b[j] = Bs[k][tx * 4 + j];
#pragma unroll
            for (int i = 0; i < 4; i++)
#pragma unroll
                for (int j = 0; j < 4; j++) acc[i][j] = fmaf(a[i], b[j], acc[i][j]);
        }
        __syncthreads();
    }

#pragma unroll
    for (int i = 0; i < 4; i++) {
        const int row = rowBase + ty * 4 + i;
        if (row < M) {
#pragma unroll
            for (int j = 0; j < 4; j++) {
                C[(size_t)row * N + colBase + tx * 4 + j] = acc[i][j];
            }
        }
    }
}

// ---------------------------------------------------------------------------
// Aggregation init: out[i, :] = b[:] + h[i, :] * dinv[i]^2   (self-loop + bias)
// ---------------------------------------------------------------------------
__global__ void init_agg_kernel(const float* __restrict__ h,
                                const float* __restrict__ dinv,
                                const float* __restrict__ bias,
                                float* __restrict__ out, int n) {
    unsigned idx = blockIdx.x * blockDim.x + threadIdx.x;  // over n*64 float4 chunks
    unsigned i = idx >> 6;
    unsigned c = (idx & 63) << 2;
    if (i >= (unsigned)n) return;
    const float di = dinv[i];
    const float w = di * di;
    float4 v = *reinterpret_cast<const float4*>(h + (size_t)i * DHID + c);
    float4 bb = *reinterpret_cast<const float4*>(bias + c);
    float4 r;
    r.x = fmaf(v.x, w, bb.x);
    r.y = fmaf(v.y, w, bb.y);
    r.z = fmaf(v.z, w, bb.z);
    r.w = fmaf(v.w, w, bb.w);
    *reinterpret_cast<float4*>(out + (size_t)i * DHID + c) = r;
}

// ---------------------------------------------------------------------------
// Edge aggregation: out[dst[e], :] += h[src[e], :] * coef[e]
// 64 threads per edge, 4 floats (one float4 gather) each.
// ---------------------------------------------------------------------------
__global__ void edge_agg_kernel(const float* __restrict__ h,
                                float* __restrict__ out,
                                const int* __restrict__ src,
                                const int* __restrict__ dst,
                                const float* __restrict__ coef, int e) {
    unsigned idx = blockIdx.x * blockDim.x + threadIdx.x;  // over e*64
    unsigned ed = idx >> 6;
    unsigned c = (idx & 63) << 2;
    if (ed >= (unsigned)e) return;
    const int s = src[ed];
    const int d = dst[ed];
    const float w = coef[ed];
    float4 v = *reinterpret_cast<const float4*>(h + (size_t)s * DHID + c);
    float* o = out + (size_t)d * DHID + c;
    atomicAdd(o + 0, v.x * w);
    atomicAdd(o + 1, v.y * w);
    atomicAdd(o + 2, v.z * w);
    atomicAdd(o + 3, v.w * w);
}

// ---------------------------------------------------------------------------
// Edge scoring: out[e] = sigmoid(dot(h[src[e],:], h[dst[e],:]))  (256 dims)
// One warp per edge, 8 dims per lane.
// ---------------------------------------------------------------------------
__global__ __launch_bounds__(256)
void score_kernel(const float* __restrict__ h,
                  const int* __restrict__ src,
                  const int* __restrict__ dst,
                  float* __restrict__ out, int e) {
    unsigned gt = blockIdx.x * blockDim.x + threadIdx.x;
    unsigned ed = gt >> 5;
    const int lane = threadIdx.x & 31;
    if (ed >= (unsigned)e) return;
    const int s = src[ed];
    const int d = dst[ed];
    const float4* ps = reinterpret_cast<const float4*>(h + (size_t)s * DHID) + lane * 2;
    const float4* pd = reinterpret_cast<const float4*>(h + (size_t)d * DHID) + lane * 2;
    float4 a0 = ps[0], a1 = ps[1];
    float4 b0 = pd[0], b1 = pd[1];
    float acc = a0.x * b0.x + a0.y * b0.y + a0.z * b0.z + a0.w * b0.w;
    acc += a1.x * b1.x + a1.y * b1.y + a1.z * b1.z + a1.w * b1.w;
#pragma unroll
    for (int off = 16; off > 0; off >>= 1)
        acc += __shfl_xor_sync(0xFFFFFFFFu, acc, off);
    if (lane == 0) out[ed] = 1.0f / (1.0f + expf(-acc));
}

// ---------------------------------------------------------------------------
// Host launcher
// ---------------------------------------------------------------------------
extern "C" void kernel_launch(void* const* d_in, const int* in_sizes, int n_in,
                              void* d_out, int out_size) {
    const float* x  = (const float*)d_in[0];   // [N, 512]
    const int*   ei = (const int*)d_in[1];     // [2, E]
    const float* W1 = (const float*)d_in[2];   // [512, 256]
    const float* b1 = (const float*)d_in[3];   // [256]
    const float* W2 = (const float*)d_in[4];   // [256, 256]
    const float* b2 = (const float*)d_in[5];   // [256]
    float* out = (float*)d_out;                // [E]

    const int N = in_sizes[0] / 512;
    const int E = in_sizes[1] / 2;
    const int* src = ei;
    const int* dst = ei + E;

    float *p_dinv, *p_coef, *p_h1, *p_agg1, *p_h2, *p_agg2;
    cudaGetSymbolAddress((void**)&p_dinv, g_dinv);
    cudaGetSymbolAddress((void**)&p_coef, g_coef);
    cudaGetSymbolAddress((void**)&p_h1,   g_h1);
    cudaGetSymbolAddress((void**)&p_agg1, g_agg1);
    cudaGetSymbolAddress((void**)&p_h2,   g_h2);
    cudaGetSymbolAddress((void**)&p_agg2, g_agg2);

    const int T = 256;

    // 1) degree -> dinv -> per-edge coefficients
    init_deg_kernel<<<(N + T - 1) / T, T>>>(p_dinv, N);
    add_deg_kernel<<<(E + T - 1) / T, T>>>(p_dinv, dst, E);
    dinv_kernel<<<(N + T - 1) / T, T>>>(p_dinv, N);
    coef_kernel<<<(E + T - 1) / T, T>>>(p_dinv, src, dst, p_coef, E);

    // 2) layer 1: h1 = x @ W1
    {
        dim3 grid(DHID / 64, (N + 63) / 64);
        gemm64x64_kernel<false><<<grid, 256>>>(x, W1, p_h1, N, 512, DHID);
    }
    // agg1 = b1 + h1*dinv^2 (self loop), then scatter edges
    init_agg_kernel<<<((unsigned)N * 64 + T - 1) / T, T>>>(p_h1, p_dinv, b1, p_agg1, N);
    edge_agg_kernel<<<((unsigned)E * 64 + T - 1) / T, T>>>(p_h1, p_agg1, src, dst, p_coef, E);

    // 3) layer 2: h2 = relu(agg1) @ W2  (relu fused into GEMM A-load)
    {
        dim3 grid(DHID / 64, (N + 63) / 64);
        gemm64x64_kernel<true><<<grid, 256>>>(p_agg1, W2, p_h2, N, DHID, DHID);
    }
    init_agg_kernel<<<((unsigned)N * 64 + T - 1) / T, T>>>(p_h2, p_dinv, b2, p_agg2, N);
    edge_agg_kernel<<<((unsigned)E * 64 + T - 1) / T, T>>>(p_h2, p_agg2, src, dst, p_coef, E);

    // 4) edge scoring
    score_kernel<<<((unsigned)E * 32 + T - 1) / T, T>>>(p_agg2, src, dst, out, E);
}

// round 2
// speedup vs baseline: 1.8727x; 1.8727x over previous
#include <cuda_runtime.h>
#include <cuda_bf16.h>
#include <math.h>

#define MAX_N 50000
#define MAX_E 800000
#define DHID 256

// Scratch device globals (no allocation allowed in kernel_launch)
__device__ int   g_cnt[MAX_N];                 // in-degree histogram (excl. self-loop)
__device__ float g_dinv[MAX_N];                // rsqrt(deg)
__device__ int   g_rowptr[MAX_N + 1];          // CSR row pointers (by dst)
__device__ int   g_off[MAX_N];                 // running offsets for scatter
__device__ int   g_esrc[MAX_E];                // src node per CSR slot
__device__ float g_ecoef[MAX_E];               // dinv[src]*dinv[dst] per CSR slot
__device__ float g_h1[(size_t)MAX_N * DHID];
__device__ float g_agg1[(size_t)MAX_N * DHID];
__device__ float g_h2[(size_t)MAX_N * DHID];
__device__ float g_agg2[(size_t)MAX_N * DHID];

// ---------------------------------------------------------------------------
// CSR build
// ---------------------------------------------------------------------------
__global__ void zero_cnt_kernel(int* cnt, int n) {
    int i = blockIdx.x * blockDim.x + threadIdx.x;
    if (i < n) cnt[i] = 0;
}

__global__ void hist_kernel(int* cnt, const int* __restrict__ dst, int e) {
    int i = blockIdx.x * blockDim.x + threadIdx.x;
    if (i < e) atomicAdd(&cnt[dst[i]], 1);
}

__global__ void dinv_kernel(const int* __restrict__ cnt, float* __restrict__ dinv, int n) {
    int i = blockIdx.x * blockDim.x + threadIdx.x;
    if (i < n) dinv[i] = rsqrtf((float)(cnt[i] + 1));  // +1 self-loop
}

// Single-block exclusive scan over n<=50176 counters; writes rowptr[0..n] and off copy.
__global__ __launch_bounds__(1024)
void scan_kernel(const int* __restrict__ cnt, int* __restrict__ rowptr,
                 int* __restrict__ off, int n) {
    __shared__ int partials[1024];
    const int tid = threadIdx.x;
    const int chunk = (n + 1023) / 1024;
    const int beg = tid * chunk;
    const int end = min(beg + chunk, n);
    int sum = 0;
    for (int i = beg; i < end; i++) sum += cnt[i];
    partials[tid] = sum;
    __syncthreads();
    // inclusive Hillis-Steele scan
    for (int d = 1; d < 1024; d <<= 1) {
        int t = (tid >= d) ? partials[tid - d] : 0;
        __syncthreads();
        partials[tid] += t;
        __syncthreads();
    }
    int run = (tid == 0) ? 0 : partials[tid - 1];
    for (int i = beg; i < end; i++) {
        rowptr[i] = run;
        off[i] = run;
        run += cnt[i];
    }
    if (tid == 1023) rowptr[n] = partials[1023];
}

__global__ void scatter_kernel(const int* __restrict__ src, const int* __restrict__ dst,
                               const float* __restrict__ dinv, int* __restrict__ off,
                               int* __restrict__ esrc, float* __restrict__ ecoef, int e) {
    int i = blockIdx.x * blockDim.x + threadIdx.x;
    if (i < e) {
        const int s = src[i];
        const int d = dst[i];
        const int pos = atomicAdd(&off[d], 1);
        esrc[pos] = s;
        ecoef[pos] = dinv[s] * dinv[d];
    }
}

// ---------------------------------------------------------------------------
// SGEMM: C[M,N] = op(A)[M,K] @ B[K,N]; 128x128 tile, 8x8/thread, BK=8,
// double-buffered. RELU fuses relu onto A loads (layer-2 input).
// N, K multiples of 8; M tail guarded.
// ---------------------------------------------------------------------------
template <bool RELU>
__global__ __launch_bounds__(256)
void sgemm128_kernel(const float* __restrict__ A, const float* __restrict__ B,
                     float* __restrict__ C, int M, int K, int N) {
    __shared__ float As[2][8][128];
    __shared__ float Bs[2][8][128];

    const int tid = threadIdx.x;
    const int rowBase = blockIdx.y * 128;
    const int colBase = blockIdx.x * 128;

    // A tile loads: 128 rows x 8 k -> 1 float4/thread
    const int ar = tid >> 1;            // 0..127
    const int ac = (tid & 1) << 2;      // 0 or 4
    // B tile loads: 8 k x 128 n -> 1 float4/thread
    const int br = tid >> 5;            // 0..7
    const int bc = (tid & 31) << 2;     // 0..124

    const int tx = (tid & 15) << 3;     // N offset of 8-wide micro tile
    const int ty = (tid >> 4) << 3;     // M offset

    float acc[8][8];
#pragma unroll
    for (int i = 0; i < 8; i++)
#pragma unroll
        for (int j = 0; j < 8; j++) acc[i][j] = 0.0f;

    const int arow = rowBase + ar;

    // prologue: stage 0
    {
        float4 av = make_float4(0.f, 0.f, 0.f, 0.f);
        if (arow < M) av = *reinterpret_cast<const float4*>(A + (size_t)arow * K + ac);
        if (RELU) {
            av.x = fmaxf(av.x, 0.f); av.y = fmaxf(av.y, 0.f);
            av.z = fmaxf(av.z, 0.f); av.w = fmaxf(av.w, 0.f);
        }
        As[0][ac + 0][ar] = av.x;
        As[0][ac + 1][ar] = av.y;
        As[0][ac + 2][ar] = av.z;
        As[0][ac + 3][ar] = av.w;
        float4 bv = *reinterpret_cast<const float4*>(B + (size_t)br * N + colBase + bc);
        *reinterpret_cast<float4*>(&Bs[0][br][bc]) = bv;
    }
    __syncthreads();

    int buf = 0;
    for (int k0 = 8; k0 <= K; k0 += 8) {
        float4 av, bv;
        const bool hasNext = (k0 < K);
        if (hasNext) {
            av = make_float4(0.f, 0.f, 0.f, 0.f);
            if (arow < M) av = *reinterpret_cast<const float4*>(A + (size_t)arow * K + k0 + ac);
            if (RELU) {
                av.x = fmaxf(av.x, 0.f); av.y = fmaxf(av.y, 0.f);
                av.z = fmaxf(av.z, 0.f); av.w = fmaxf(av.w, 0.f);
            }
            bv = *reinterpret_cast<const float4*>(B + (size_t)(k0 + br) * N + colBase + bc);
        }

#pragma unroll
        for (int k = 0; k < 8; k++) {
            float4 a0 = *reinterpret_cast<const float4*>(&As[buf][k][ty]);
            float4 a1 = *reinterpret_cast<const float4*>(&As[buf][k][ty + 4]);
            float4 b0 = *reinterpret_cast<const float4*>(&Bs[buf][k][tx]);
            float4 b1 = *reinterpret_cast<const float4*>(&Bs[buf][k][tx + 4]);
            float a[8] = {a0.x, a0.y, a0.z, a0.w, a1.x, a1.y, a1.z, a1.w};
            float b[8] = {b0.x, b0.y, b0.z, b0.w, b1.x, b1.y, b1.z, b1.w};
#pragma unroll
            for (int i = 0; i < 8; i++)
#pragma unroll
                for (int j = 0; j < 8; j++) acc[i][j] = fmaf(a[i], b[j], acc[i][j]);
        }

        if (hasNext) {
            As[buf ^ 1][ac + 0][ar] = av.x;
            As[buf ^ 1][ac + 1][ar] = av.y;
            As[buf ^ 1][ac + 2][ar] = av.z;
            As[buf ^ 1][ac + 3][ar] = av.w;
            *reinterpret_cast<float4*>(&Bs[buf ^ 1][br][bc]) = bv;
            __syncthreads();
            buf ^= 1;
        }
    }

#pragma unroll
    for (int i = 0; i < 8; i++) {
        const int row = rowBase + ty + i;
        if (row < M) {
            float4 o0 = make_float4(acc[i][0], acc[i][1], acc[i][2], acc[i][3]);
            float4 o1 = make_float4(acc[i][4], acc[i][5], acc[i][6], acc[i][7]);
            *reinterpret_cast<float4*>(C + (size_t)row * N + colBase + tx) = o0;
            *reinterpret_cast<float4*>(C + (size_t)row * N + colBase + tx + 4) = o1;
        }
    }
}

// ---------------------------------------------------------------------------
// CSR aggregation: out[n,:] = bias + h[n,:]*dinv[n]^2 + sum_e coef[e]*h[esrc[e],:]
// 64 threads per node, 4 dims (1 float4) per thread. No atomics.
// ---------------------------------------------------------------------------
__global__ __launch_bounds__(256)
void agg_csr_kernel(const float* __restrict__ h, const float* __restrict__ bias,
                    const float* __restrict__ dinv,
                    const int* __restrict__ rowptr, const int* __restrict__ esrc,
                    const float* __restrict__ ecoef,
                    float* __restrict__ out, int n) {
    const int node = blockIdx.x * 4 + (threadIdx.x >> 6);
    if (node >= n) return;
    const int c = (threadIdx.x & 63) << 2;

    const float di = dinv[node];
    const float wself = di * di;
    float4 hv = *reinterpret_cast<const float4*>(h + (size_t)node * DHID + c);
    float4 bb = *reinterpret_cast<const float4*>(bias + c);
    float4 acc;
    acc.x = fmaf(hv.x, wself, bb.x);
    acc.y = fmaf(hv.y, wself, bb.y);
    acc.z = fmaf(hv.z, wself, bb.z);
    acc.w = fmaf(hv.w, wself, bb.w);

    const int beg = rowptr[node];
    const int end = rowptr[node + 1];
    int e = beg;
    for (; e + 2 <= end; e += 2) {
        const int s0 = esrc[e];
        const int s1 = esrc[e + 1];
        const float c0 = ecoef[e];
        const float c1 = ecoef[e + 1];
        float4 v0 = *reinterpret_cast<const float4*>(h + (size_t)s0 * DHID + c);
        float4 v1 = *reinterpret_cast<const float4*>(h + (size_t)s1 * DHID + c);
        acc.x += c0 * v0.x + c1 * v1.x;
        acc.y += c0 * v0.y + c1 * v1.y;
        acc.z += c0 * v0.z + c1 * v1.z;
        acc.w += c0 * v0.w + c1 * v1.w;
    }
    if (e < end) {
        const int s0 = esrc[e];
        const float c0 = ecoef[e];
        float4 v0 = *reinterpret_cast<const float4*>(h + (size_t)s0 * DHID + c);
        acc.x += c0 * v0.x;
        acc.y += c0 * v0.y;
        acc.z += c0 * v0.z;
        acc.w += c0 * v0.w;
    }
    *reinterpret_cast<float4*>(out + (size_t)node * DHID + c) = acc;
}

// ---------------------------------------------------------------------------
// Edge scoring: out[e] = sigmoid(dot(h[src[e],:], h[dst[e],:]))
// ---------------------------------------------------------------------------
__global__ __launch_bounds__(256)
void score_kernel(const float* __restrict__ h,
                  const int* __restrict__ src,
                  const int* __restrict__ dst,
                  float* __restrict__ out, int e) {
    unsigned gt = blockIdx.x * blockDim.x + threadIdx.x;
    unsigned ed = gt >> 5;
    const int lane = threadIdx.x & 31;
    if (ed >= (unsigned)e) return;
    const int s = src[ed];
    const int d = dst[ed];
    const float4* ps = reinterpret_cast<const float4*>(h + (size_t)s * DHID) + lane * 2;
    const float4* pd = reinterpret_cast<const float4*>(h + (size_t)d * DHID) + lane * 2;
    float4 a0 = ps[0], a1 = ps[1];
    float4 b0 = pd[0], b1 = pd[1];
    float acc = a0.x * b0.x + a0.y * b0.y + a0.z * b0.z + a0.w * b0.w;
    acc += a1.x * b1.x + a1.y * b1.y + a1.z * b1.z + a1.w * b1.w;
#pragma unroll
    for (int off = 16; off > 0; off >>= 1)
        acc += __shfl_xor_sync(0xFFFFFFFFu, acc, off);
    if (lane == 0) out[ed] = 1.0f / (1.0f + expf(-acc));
}

// ---------------------------------------------------------------------------
// Host launcher
// ---------------------------------------------------------------------------
extern "C" void kernel_launch(void* const* d_in, const int* in_sizes, int n_in,
                              void* d_out, int out_size) {
    const float* x  = (const float*)d_in[0];   // [N, 512]
    const int*   ei = (const int*)d_in[1];     // [2, E]
    const float* W1 = (const float*)d_in[2];   // [512, 256]
    const float* b1 = (const float*)d_in[3];   // [256]
    const float* W2 = (const float*)d_in[4];   // [256, 256]
    const float* b2 = (const float*)d_in[5];   // [256]
    float* out = (float*)d_out;                // [E]

    const int N = in_sizes[0] / 512;
    const int E = in_sizes[1] / 2;
    const int* src = ei;
    const int* dst = ei + E;

    int *p_cnt, *p_rowptr, *p_off, *p_esrc;
    float *p_dinv, *p_ecoef, *p_h1, *p_agg1, *p_h2, *p_agg2;
    cudaGetSymbolAddress((void**)&p_cnt,    g_cnt);
    cudaGetSymbolAddress((void**)&p_dinv,   g_dinv);
    cudaGetSymbolAddress((void**)&p_rowptr, g_rowptr);
    cudaGetSymbolAddress((void**)&p_off,    g_off);
    cudaGetSymbolAddress((void**)&p_esrc,   g_esrc);
    cudaGetSymbolAddress((void**)&p_ecoef,  g_ecoef);
    cudaGetSymbolAddress((void**)&p_h1,     g_h1);
    cudaGetSymbolAddress((void**)&p_agg1,   g_agg1);
    cudaGetSymbolAddress((void**)&p_h2,     g_h2);
    cudaGetSymbolAddress((void**)&p_agg2,   g_agg2);

    const int T = 256;

    // 1) CSR build + normalization
    zero_cnt_kernel<<<(N + T - 1) / T, T>>>(p_cnt, N);
    hist_kernel<<<(E + T - 1) / T, T>>>(p_cnt, dst, E);
    dinv_kernel<<<(N + T - 1) / T, T>>>(p_cnt, p_dinv, N);
    scan_kernel<<<1, 1024>>>(p_cnt, p_rowptr, p_off, N);
    scatter_kernel<<<(E + T - 1) / T, T>>>(src, dst, p_dinv, p_off, p_esrc, p_ecoef, E);

    // 2) layer 1: h1 = x @ W1 ; agg1 = bias + self + neighbors
    {
        dim3 grid(DHID / 128, (N + 127) / 128);
        sgemm128_kernel<false><<<grid, 256>>>(x, W1, p_h1, N, 512, DHID);
    }
    agg_csr_kernel<<<(N + 3) / 4, 256>>>(p_h1, b1, p_dinv, p_rowptr, p_esrc, p_ecoef, p_agg1, N);

    // 3) layer 2: h2 = relu(agg1) @ W2 ; agg2
    {
        dim3 grid(DHID / 128, (N + 127) / 128);
        sgemm128_kernel<true><<<grid, 256>>>(p_agg1, W2, p_h2, N, DHID, DHID);
    }
    agg_csr_kernel<<<(N + 3) / 4, 256>>>(p_h2, b2, p_dinv, p_rowptr, p_esrc, p_ecoef, p_agg2, N);

    // 4) edge scoring
    score_kernel<<<((unsigned)E * 32 + T - 1) / T, T>>>(p_agg2, src, dst, out, E);
}

// round 4
// speedup vs baseline: 2.5521x; 1.3628x over previous
#include <cuda_runtime.h>
#include <cuda_bf16.h>
#include <stdint.h>
#include <math.h>

#define MAX_N 50000
#define MAX_E 800000
#define DHID 256
#define NB_SCAN 128

// Scratch device globals
__device__ int   g_cnt[MAX_N];
__device__ float g_dinv[MAX_N];
__device__ int   g_rowptr[MAX_N + 1];
__device__ int   g_off[MAX_N];
__device__ int   g_blocksum[NB_SCAN];
__device__ int   g_blockoff[NB_SCAN];
__device__ int   g_esrc[MAX_E];
__device__ float g_ecoef[MAX_E];
__device__ float g_h1[(size_t)MAX_N * DHID];
__device__ float g_agg1[(size_t)MAX_N * DHID];
__device__ float g_h2[(size_t)MAX_N * DHID];
__device__ float g_agg2[(size_t)MAX_N * DHID];

// ---------------------------------------------------------------------------
// CSR build
// ---------------------------------------------------------------------------
__global__ void zero_cnt_kernel(int* cnt, int n) {
    int i = blockIdx.x * blockDim.x + threadIdx.x;
    if (i < n) cnt[i] = 0;
}

__global__ void hist_kernel(int* cnt, const int* __restrict__ dst, int e) {
    int i = blockIdx.x * blockDim.x + threadIdx.x;
    if (i < e) atomicAdd(&cnt[dst[i]], 1);
}

__global__ void dinv_kernel(const int* __restrict__ cnt, float* __restrict__ dinv, int n) {
    int i = blockIdx.x * blockDim.x + threadIdx.x;
    if (i < n) dinv[i] = rsqrtf((float)(cnt[i] + 1));
}

// Phase 1: per-block partial sums over chunks of cnt
__global__ __launch_bounds__(256)
void scan_p1_kernel(const int* __restrict__ cnt, int* __restrict__ blocksum, int n) {
    __shared__ int red[256];
    const int chunk = (n + NB_SCAN - 1) / NB_SCAN;
    const int beg = blockIdx.x * chunk;
    const int end = min(beg + chunk, n);
    int s = 0;
    for (int i = beg + threadIdx.x; i < end; i += 256) s += cnt[i];
    red[threadIdx.x] = s;
    __syncthreads();
    for (int d = 128; d > 0; d >>= 1) {
        if (threadIdx.x < d) red[threadIdx.x] += red[threadIdx.x + d];
        __syncthreads();
    }
    if (threadIdx.x == 0) blocksum[blockIdx.x] = red[0];
}

// Phase 2: exclusive scan of NB_SCAN block sums (one block); writes rowptr[n]=total
__global__ __launch_bounds__(NB_SCAN)
void scan_p2_kernel(const int* __restrict__ blocksum, int* __restrict__ blockoff,
                    int* __restrict__ rowptr, int n) {
    __shared__ int sh[NB_SCAN];
    const int t = threadIdx.x;
    sh[t] = blocksum[t];
    __syncthreads();
    for (int d = 1; d < NB_SCAN; d <<= 1) {
        int v = (t >= d) ? sh[t - d] : 0;
        __syncthreads();
        sh[t] += v;
        __syncthreads();
    }
    blockoff[t] = (t == 0) ? 0 : sh[t - 1];
    if (t == NB_SCAN - 1) rowptr[n] = sh[NB_SCAN - 1];
}

// Phase 3: per-block exclusive scan of its chunk, seeded by blockoff
__global__ __launch_bounds__(256)
void scan_p3_kernel(const int* __restrict__ cnt, const int* __restrict__ blockoff,
                    int* __restrict__ rowptr, int* __restrict__ off, int n) {
    __shared__ int sh[256];
    const int chunk = (n + NB_SCAN - 1) / NB_SCAN;
    const int beg = blockIdx.x * chunk;
    const int end = min(beg + chunk, n);
    int running = blockoff[blockIdx.x];
    for (int base = beg; base < end; base += 256) {
        const int i = base + threadIdx.x;
        int v = (i < end) ? cnt[i] : 0;
        sh[threadIdx.x] = v;
        __syncthreads();
        // inclusive Hillis-Steele
        for (int d = 1; d < 256; d <<= 1) {
            int t2 = (threadIdx.x >= d) ? sh[threadIdx.x - d] : 0;
            __syncthreads();
            sh[threadIdx.x] += t2;
            __syncthreads();
        }
        if (i < end) {
            const int excl = sh[threadIdx.x] - v;
            rowptr[i] = running + excl;
            off[i] = running + excl;
        }
        running += sh[255];
        __syncthreads();
    }
}

__global__ void scatter_kernel(const int* __restrict__ src, const int* __restrict__ dst,
                               const float* __restrict__ dinv, int* __restrict__ off,
                               int* __restrict__ esrc, float* __restrict__ ecoef, int e) {
    int i = blockIdx.x * blockDim.x + threadIdx.x;
    if (i < e) {
        const int s = src[i];
        const int d = dst[i];
        const int pos = atomicAdd(&off[d], 1);
        esrc[pos] = s;
        ecoef[pos] = dinv[s] * dinv[d];
    }
}

// ---------------------------------------------------------------------------
// Tensor-core GEMM with bf16x2 error-compensated split.
// C[M,N] = op(A)[M,K] @ B[K,N], fp32 in/out, fp32 accumulate.
// A = Ah + Al (bf16 each), B = Bh + Bl; C ~= Ah*Bh + Ah*Bl + Al*Bh.
// CTA tile 128(M) x 64(N), BK=16, 8 warps (4 m-warps x 2 n-warps),
// warp tile 32x32, mma.sync m16n8k16. Double-buffered smem.
// ---------------------------------------------------------------------------
#define A_PAD 24   // bf16 elems per row (16 data + 8 pad) -> 48B row stride
#define B_PAD 72   // bf16 elems per row (64 data + 8 pad) -> 144B row stride

__device__ __forceinline__ void ldsm_x4(uint32_t addr, uint32_t& r0, uint32_t& r1,
                                        uint32_t& r2, uint32_t& r3) {
    asm volatile("ldmatrix.sync.aligned.m8n8.x4.shared.b16 {%0,%1,%2,%3}, [%4];"
                 : "=r"(r0), "=r"(r1), "=r"(r2), "=r"(r3) : "r"(addr));
}
__device__ __forceinline__ void ldsm_x4_t(uint32_t addr, uint32_t& r0, uint32_t& r1,
                                          uint32_t& r2, uint32_t& r3) {
    asm volatile("ldmatrix.sync.aligned.m8n8.x4.trans.shared.b16 {%0,%1,%2,%3}, [%4];"
                 : "=r"(r0), "=r"(r1), "=r"(r2), "=r"(r3) : "r"(addr));
}
__device__ __forceinline__ void mma_bf16(float* d, const uint32_t* a, const uint32_t* b) {
    asm volatile("mma.sync.aligned.m16n8k16.row.col.f32.bf16.bf16.f32 "
                 "{%0,%1,%2,%3}, {%4,%5,%6,%7}, {%8,%9}, {%0,%1,%2,%3};"
                 : "+f"(d[0]), "+f"(d[1]), "+f"(d[2]), "+f"(d[3])
                 : "r"(a[0]), "r"(a[1]), "r"(a[2]), "r"(a[3]), "r"(b[0]), "r"(b[1]));
}

__device__ __forceinline__ void split_store(__nv_bfloat16* ph, __nv_bfloat16* pl, float v) {
    __nv_bfloat16 hi = __float2bfloat16(v);
    float r = v - __bfloat162float(hi);
    *ph = hi;
    *pl = __float2bfloat16(r);
}

template <bool RELU>
__global__ __launch_bounds__(256)
void mma_gemm_kernel(const float* __restrict__ A, const float* __restrict__ B,
                     float* __restrict__ C, int M, int K, int N) {
    __shared__ __nv_bfloat16 Ah[2][128][A_PAD];
    __shared__ __nv_bfloat16 Al[2][128][A_PAD];
    __shared__ __nv_bfloat16 Bh[2][16][B_PAD];
    __shared__ __nv_bfloat16 Bl[2][16][B_PAD];

    const int tid = threadIdx.x;
    const int wid = tid >> 5;
    const int lane = tid & 31;
    const int warp_m = wid & 3;     // 0..3 -> 32-row slices
    const int warp_n = wid >> 2;    // 0..1 -> 32-col slices
    const int rowBase = blockIdx.y * 128;
    const int colBase = blockIdx.x * 64;

    // staging maps
    const int a_r = tid >> 1;            // 0..127
    const int a_k = (tid & 1) << 3;      // 0 or 8
    const int b_r = tid >> 4;            // 0..15
    const int b_c = (tid & 15) << 2;     // 0..60

    const int arow = rowBase + a_r;

    // ldmatrix lane address components
    const int lrow = lane & 7;
    const int lmat = lane >> 3;
    const int a_mloc = ((lmat & 1) << 3) + lrow;
    const int a_khalf = lmat >> 1;
    const int b_krow = ((lmat & 1) << 3) + lrow;
    const int b_nhalf = lmat >> 1;

    float acc[2][4][4];  // [mf][g*2+h][4]
#pragma unroll
    for (int i = 0; i < 2; i++)
#pragma unroll
        for (int j = 0; j < 4; j++)
#pragma unroll
            for (int q = 0; q < 4; q++) acc[i][j][q] = 0.0f;

    // ---- prologue: stage k-tile 0 into buffer 0 ----
    {
        float4 av0 = make_float4(0.f, 0.f, 0.f, 0.f), av1 = av0;
        if (arow < M) {
            av0 = *reinterpret_cast<const float4*>(A + (size_t)arow * K + a_k);
            av1 = *reinterpret_cast<const float4*>(A + (size_t)arow * K + a_k + 4);
        }
        if (RELU) {
            av0.x = fmaxf(av0.x, 0.f); av0.y = fmaxf(av0.y, 0.f);
            av0.z = fmaxf(av0.z, 0.f); av0.w = fmaxf(av0.w, 0.f);
            av1.x = fmaxf(av1.x, 0.f); av1.y = fmaxf(av1.y, 0.f);
            av1.z = fmaxf(av1.z, 0.f); av1.w = fmaxf(av1.w, 0.f);
        }
        split_store(&Ah[0][a_r][a_k + 0], &Al[0][a_r][a_k + 0], av0.x);
        split_store(&Ah[0][a_r][a_k + 1], &Al[0][a_r][a_k + 1], av0.y);
        split_store(&Ah[0][a_r][a_k + 2], &Al[0][a_r][a_k + 2], av0.z);
        split_store(&Ah[0][a_r][a_k + 3], &Al[0][a_r][a_k + 3], av0.w);
        split_store(&Ah[0][a_r][a_k + 4], &Al[0][a_r][a_k + 4], av1.x);
        split_store(&Ah[0][a_r][a_k + 5], &Al[0][a_r][a_k + 5], av1.y);
        split_store(&Ah[0][a_r][a_k + 6], &Al[0][a_r][a_k + 6], av1.z);
        split_store(&Ah[0][a_r][a_k + 7], &Al[0][a_r][a_k + 7], av1.w);

        float4 bv = *reinterpret_cast<const float4*>(B + (size_t)b_r * N + colBase + b_c);
        split_store(&Bh[0][b_r][b_c + 0], &Bl[0][b_r][b_c + 0], bv.x);
        split_store(&Bh[0][b_r][b_c + 1], &Bl[0][b_r][b_c + 1], bv.y);
        split_store(&Bh[0][b_r][b_c + 2], &Bl[0][b_r][b_c + 2], bv.z);
        split_store(&Bh[0][b_r][b_c + 3], &Bl[0][b_r][b_c + 3], bv.w);
    }
    __syncthreads();

    int buf = 0;
    for (int k0 = 16; k0 <= K; k0 += 16) {
        const bool hasNext = (k0 < K);
        float4 av0, av1, bv;
        if (hasNext) {
            av0 = make_float4(0.f, 0.f, 0.f, 0.f); av1 = av0;
            if (arow < M) {
                av0 = *reinterpret_cast<const float4*>(A + (size_t)arow * K + k0 + a_k);
                av1 = *reinterpret_cast<const float4*>(A + (size_t)arow * K + k0 + a_k + 4);
            }
            if (RELU) {
                av0.x = fmaxf(av0.x, 0.f); av0.y = fmaxf(av0.y, 0.f);
                av0.z = fmaxf(av0.z, 0.f); av0.w = fmaxf(av0.w, 0.f);
                av1.x = fmaxf(av1.x, 0.f); av1.y = fmaxf(av1.y, 0.f);
                av1.z = fmaxf(av1.z, 0.f); av1.w = fmaxf(av1.w, 0.f);
            }
            bv = *reinterpret_cast<const float4*>(B + (size_t)(k0 + b_r) * N + colBase + b_c);
        }

        // ---- compute on buffer `buf` ----
        uint32_t ah[2][4], al[2][4];
#pragma unroll
        for (int mf = 0; mf < 2; mf++) {
            const int m_base = warp_m * 32 + mf * 16;
            uint32_t addr_h = (uint32_t)__cvta_generic_to_shared(
                &Ah[buf][m_base + a_mloc][a_khalf * 8]);
            ldsm_x4(addr_h, ah[mf][0], ah[mf][1], ah[mf][2], ah[mf][3]);
            uint32_t addr_l = (uint32_t)__cvta_generic_to_shared(
                &Al[buf][m_base + a_mloc][a_khalf * 8]);
            ldsm_x4(addr_l, al[mf][0], al[mf][1], al[mf][2], al[mf][3]);
        }
        uint32_t bh[2][4], bl[2][4];
#pragma unroll
        for (int g = 0; g < 2; g++) {
            const int n_base = warp_n * 32 + g * 16;
            uint32_t addr_h = (uint32_t)__cvta_generic_to_shared(
                &Bh[buf][b_krow][n_base + b_nhalf * 8]);
            ldsm_x4_t(addr_h, bh[g][0], bh[g][1], bh[g][2], bh[g][3]);
            uint32_t addr_l = (uint32_t)__cvta_generic_to_shared(
                &Bl[buf][b_krow][n_base + b_nhalf * 8]);
            ldsm_x4_t(addr_l, bl[g][0], bl[g][1], bl[g][2], bl[g][3]);
        }
#pragma unroll
        for (int mf = 0; mf < 2; mf++) {
#pragma unroll
            for (int g = 0; g < 2; g++) {
#pragma unroll
                for (int h = 0; h < 2; h++) {
                    float* d = acc[mf][g * 2 + h];
                    const uint32_t bhp[2] = {bh[g][h * 2], bh[g][h * 2 + 1]};
                    const uint32_t blp[2] = {bl[g][h * 2], bl[g][h * 2 + 1]};
                    mma_bf16(d, ah[mf], bhp);   // Ah*Bh
                    mma_bf16(d, ah[mf], blp);   // Ah*Bl
                    mma_bf16(d, al[mf], bhp);   // Al*Bh
                }
            }
        }

        if (hasNext) {
            const int nb = buf ^ 1;
            split_store(&Ah[nb][a_r][a_k + 0], &Al[nb][a_r][a_k + 0], av0.x);
            split_store(&Ah[nb][a_r][a_k + 1], &Al[nb][a_r][a_k + 1], av0.y);
            split_store(&Ah[nb][a_r][a_k + 2], &Al[nb][a_r][a_k + 2], av0.z);
            split_store(&Ah[nb][a_r][a_k + 3], &Al[nb][a_r][a_k + 3], av0.w);
            split_store(&Ah[nb][a_r][a_k + 4], &Al[nb][a_r][a_k + 4], av1.x);
            split_store(&Ah[nb][a_r][a_k + 5], &Al[nb][a_r][a_k + 5], av1.y);
            split_store(&Ah[nb][a_r][a_k + 6], &Al[nb][a_r][a_k + 6], av1.z);
            split_store(&Ah[nb][a_r][a_k + 7], &Al[nb][a_r][a_k + 7], av1.w);
            split_store(&Bh[nb][b_r][b_c + 0], &Bl[nb][b_r][b_c + 0], bv.x);
            split_store(&Bh[nb][b_r][b_c + 1], &Bl[nb][b_r][b_c + 1], bv.y);
            split_store(&Bh[nb][b_r][b_c + 2], &Bl[nb][b_r][b_c + 2], bv.z);
            split_store(&Bh[nb][b_r][b_c + 3], &Bl[nb][b_r][b_c + 3], bv.w);
            __syncthreads();
            buf ^= 1;
        }
    }

    // ---- epilogue ----
    const int lq = lane >> 2;
    const int lr = lane & 3;
#pragma unroll
    for (int mf = 0; mf < 2; mf++) {
#pragma unroll
        for (int g = 0; g < 2; g++) {
#pragma unroll
            for (int h = 0; h < 2; h++) {
                const float* d = acc[mf][g * 2 + h];
                const int col = colBase + warp_n * 32 + g * 16 + h * 8 + lr * 2;
                const int r0 = rowBase + warp_m * 32 + mf * 16 + lq;
                if (r0 < M)
                    *reinterpret_cast<float2*>(C + (size_t)r0 * N + col) =
                        make_float2(d[0], d[1]);
                const int r1 = r0 + 8;
                if (r1 < M)
                    *reinterpret_cast<float2*>(C + (size_t)r1 * N + col) =
                        make_float2(d[2], d[3]);
            }
        }
    }
}

// ---------------------------------------------------------------------------
// CSR aggregation (no atomics): out[n,:] = bias + h[n,:]*dinv^2 + sum coef*h[src,:]
// ---------------------------------------------------------------------------
__global__ __launch_bounds__(256)
void agg_csr_kernel(const float* __restrict__ h, const float* __restrict__ bias,
                    const float* __restrict__ dinv,
                    const int* __restrict__ rowptr, const int* __restrict__ esrc,
                    const float* __restrict__ ecoef,
                    float* __restrict__ out, int n) {
    const int node = blockIdx.x * 4 + (threadIdx.x >> 6);
    if (node >= n) return;
    const int c = (threadIdx.x & 63) << 2;

    const float di = dinv[node];
    const float wself = di * di;
    float4 hv = *reinterpret_cast<const float4*>(h + (size_t)node * DHID + c);
    float4 bb = *reinterpret_cast<const float4*>(bias + c);
    float4 acc;
    acc.x = fmaf(hv.x, wself, bb.x);
    acc.y = fmaf(hv.y, wself, bb.y);
    acc.z = fmaf(hv.z, wself, bb.z);
    acc.w = fmaf(hv.w, wself, bb.w);

    const int beg = rowptr[node];
    const int end = rowptr[node + 1];
    int e = beg;
    for (; e + 2 <= end; e += 2) {
        const int s0 = esrc[e];
        const int s1 = esrc[e + 1];
        const float c0 = ecoef[e];
        const float c1 = ecoef[e + 1];
        float4 v0 = *reinterpret_cast<const float4*>(h + (size_t)s0 * DHID + c);
        float4 v1 = *reinterpret_cast<const float4*>(h + (size_t)s1 * DHID + c);
        acc.x += c0 * v0.x + c1 * v1.x;
        acc.y += c0 * v0.y + c1 * v1.y;
        acc.z += c0 * v0.z + c1 * v1.z;
        acc.w += c0 * v0.w + c1 * v1.w;
    }
    if (e < end) {
        const int s0 = esrc[e];
        const float c0 = ecoef[e];
        float4 v0 = *reinterpret_cast<const float4*>(h + (size_t)s0 * DHID + c);
        acc.x += c0 * v0.x;
        acc.y += c0 * v0.y;
        acc.z += c0 * v0.z;
        acc.w += c0 * v0.w;
    }
    *reinterpret_cast<float4*>(out + (size_t)node * DHID + c) = acc;
}

// ---------------------------------------------------------------------------
// Edge scoring
// ---------------------------------------------------------------------------
__global__ __launch_bounds__(256)
void score_kernel(const float* __restrict__ h,
                  const int* __restrict__ src,
                  const int* __restrict__ dst,
                  float* __restrict__ out, int e) {
    unsigned gt = blockIdx.x * blockDim.x + threadIdx.x;
    unsigned ed = gt >> 5;
    const int lane = threadIdx.x & 31;
    if (ed >= (unsigned)e) return;
    const int s = src[ed];
    const int d = dst[ed];
    const float4* ps = reinterpret_cast<const float4*>(h + (size_t)s * DHID) + lane * 2;
    const float4* pd = reinterpret_cast<const float4*>(h + (size_t)d * DHID) + lane * 2;
    float4 a0 = ps[0], a1 = ps[1];
    float4 b0 = pd[0], b1 = pd[1];
    float acc = a0.x * b0.x + a0.y * b0.y + a0.z * b0.z + a0.w * b0.w;
    acc += a1.x * b1.x + a1.y * b1.y + a1.z * b1.z + a1.w * b1.w;
#pragma unroll
    for (int off = 16; off > 0; off >>= 1)
        acc += __shfl_xor_sync(0xFFFFFFFFu, acc, off);
    if (lane == 0) out[ed] = 1.0f / (1.0f + expf(-acc));
}

// ---------------------------------------------------------------------------
// Host launcher
// ---------------------------------------------------------------------------
extern "C" void kernel_launch(void* const* d_in, const int* in_sizes, int n_in,
                              void* d_out, int out_size) {
    const float* x  = (const float*)d_in[0];
    const int*   ei = (const int*)d_in[1];
    const float* W1 = (const float*)d_in[2];
    const float* b1 = (const float*)d_in[3];
    const float* W2 = (const float*)d_in[4];
    const float* b2 = (const float*)d_in[5];
    float* out = (float*)d_out;

    const int N = in_sizes[0] / 512;
    const int E = in_sizes[1] / 2;
    const int* src = ei;
    const int* dst = ei + E;

    int *p_cnt, *p_rowptr, *p_off, *p_esrc, *p_bsum, *p_boff;
    float *p_dinv, *p_ecoef, *p_h1, *p_agg1, *p_h2, *p_agg2;
    cudaGetSymbolAddress((void**)&p_cnt,    g_cnt);
    cudaGetSymbolAddress((void**)&p_dinv,   g_dinv);
    cudaGetSymbolAddress((void**)&p_rowptr, g_rowptr);
    cudaGetSymbolAddress((void**)&p_off,    g_off);
    cudaGetSymbolAddress((void**)&p_bsum,   g_blocksum);
    cudaGetSymbolAddress((void**)&p_boff,   g_blockoff);
    cudaGetSymbolAddress((void**)&p_esrc,   g_esrc);
    cudaGetSymbolAddress((void**)&p_ecoef,  g_ecoef);
    cudaGetSymbolAddress((void**)&p_h1,     g_h1);
    cudaGetSymbolAddress((void**)&p_agg1,   g_agg1);
    cudaGetSymbolAddress((void**)&p_h2,     g_h2);
    cudaGetSymbolAddress((void**)&p_agg2,   g_agg2);

    const int T = 256;

    // 1) CSR build + normalization (parallel scan)
    zero_cnt_kernel<<<(N + T - 1) / T, T>>>(p_cnt, N);
    hist_kernel<<<(E + T - 1) / T, T>>>(p_cnt, dst, E);
    dinv_kernel<<<(N + T - 1) / T, T>>>(p_cnt, p_dinv, N);
    scan_p1_kernel<<<NB_SCAN, 256>>>(p_cnt, p_bsum, N);
    scan_p2_kernel<<<1, NB_SCAN>>>(p_bsum, p_boff, p_rowptr, N);
    scan_p3_kernel<<<NB_SCAN, 256>>>(p_cnt, p_boff, p_rowptr, p_off, N);
    scatter_kernel<<<(E + T - 1) / T, T>>>(src, dst, p_dinv, p_off, p_esrc, p_ecoef, E);

    // 2) layer 1: h1 = x @ W1 (tensor cores, bf16x2 split)
    {
        dim3 grid(DHID / 64, (N + 127) / 128);
        mma_gemm_kernel<false><<<grid, 256>>>(x, W1, p_h1, N, 512, DHID);
    }
    agg_csr_kernel<<<(N + 3) / 4, 256>>>(p_h1, b1, p_dinv, p_rowptr, p_esrc, p_ecoef, p_agg1, N);

    // 3) layer 2: h2 = relu(agg1) @ W2
    {
        dim3 grid(DHID / 64, (N + 127) / 128);
        mma_gemm_kernel<true><<<grid, 256>>>(p_agg1, W2, p_h2, N, DHID, DHID);
    }
    agg_csr_kernel<<<(N + 3) / 4, 256>>>(p_h2, b2, p_dinv, p_rowptr, p_esrc, p_ecoef, p_agg2, N);

    // 4) edge scoring
    score_kernel<<<((unsigned)E * 32 + T - 1) / T, T>>>(p_agg2, src, dst, out, E);
}